// round 11
// baseline (speedup 1.0000x reference)
#include <cuda_runtime.h>
#include <math.h>
#include <cstdint>

// Problem constants
#define BATCH 2
#define SEQL 2048
#define NTOK (BATCH * SEQL)          // 4096
#define DMODEL 512
#define ED 1024
#define DSTATE 16
#define DCONV 4
#define DTRANK 32
#define NLAYERS 2

// Scratch buffers (no cudaMalloc allowed)
__device__ float g_xz[NTOK * 2 * ED];
__device__ float g_xic[NTOK * ED];
__device__ float g_dbc[NTOK * 64];
__device__ float g_dbcp[8 * NTOK * 64];   // split-K partials for x_proj
__device__ float g_delta[NTOK * ED];
__device__ float g_y[NTOK * ED];

__device__ __forceinline__ float softplus_f(float v) {
    return (v > 20.f) ? v : log1pf(__expf(v));
}
__device__ __forceinline__ float silu_f(float v) {
    return __fdividef(v, 1.f + __expf(-v));
}

// ---------------------------------------------------------------------------
// Packed fp32 helpers (Blackwell f32x2)
// ---------------------------------------------------------------------------
typedef unsigned long long u64t;

__device__ __forceinline__ u64t dup2f(float v) {
    u64t r; unsigned u = __float_as_uint(v);
    asm("mov.b64 %0, {%1, %1};" : "=l"(r) : "r"(u));
    return r;
}
__device__ __forceinline__ void ffma2(u64t& c, u64t a, u64t b) {
    asm("fma.rn.f32x2 %0, %1, %2, %0;" : "+l"(c) : "l"(a), "l"(b));
}
__device__ __forceinline__ float2 unpack2(u64t p) {
    unsigned lo, hi;
    asm("mov.b64 {%0, %1}, %2;" : "=r"(lo), "=r"(hi) : "l"(p));
    return make_float2(__uint_as_float(lo), __uint_as_float(hi));
}

// ---------------------------------------------------------------------------
// fp32 FFMA2 GEMM:  C[M,N] (=, +=) A[M,K] @ W[N,K]^T
// BM=128, BN=TILE_N (128/64), BK=16, 256 threads, smem k-major double buffer.
// B-fragment columns split into 4-wide groups 32 apart (TC=8): conflict-free.
// ONE __syncthreads per k-tile: a warp reaches STS of tile kt+2 (overwriting
// buf(kt)) only after passing the top barrier of kt+1, which requires all
// warps to have finished compute(kt).
// Options: +bias, +softplus, NORMW, ROWSCALE, SPLITK, SILUZ (silu on n0>=ED).
// ---------------------------------------------------------------------------
template <int TILE_N, bool BIAS, bool ACCUM, bool SOFTPLUS, bool NORMW,
          bool ROWSCALE, int SPLITK = 1, bool SILUZ = false>
__global__ __launch_bounds__(256) void fgemm(
    const float* __restrict__ A, int lda,
    const float* __restrict__ W, int ldw,
    const float* __restrict__ bias,
    const float* __restrict__ nw,
    float* __restrict__ C, int ldc, int K)
{
    constexpr int BK = 16, STA = 132, STB = TILE_N + 4;
    constexpr int NBCH = TILE_N / 64;
    constexpr int TC = TILE_N / 16;
    constexpr int NQ = TC / 4;

    __shared__ float sA[2][BK * STA];
    __shared__ float sB[2][BK * STB];
    __shared__ float rbuf[128];

    const int tid = threadIdx.x;
    const int wid = tid >> 5, lane = tid & 31;
    const int ly = lane >> 3, lx = lane & 7;
    const int wy = wid >> 1, wx = wid & 1;
    const int rb = wy * 32 + ly * 8;
    const int cbase = wx * (TILE_N / 2) + lx * 4;
    const int m0 = blockIdx.y * 128;
    const int n0 = blockIdx.x * TILE_N;

    if (SPLITK > 1) {
        const int ks = blockIdx.z * (K / SPLITK);
        A += ks; W += ks;
        C += (size_t)blockIdx.z * gridDim.y * 128 * ldc;
        K = K / SPLITK;
    }

    const int arow = tid >> 2, aq = tid & 3;

    u64t cpk[4][TC] = {};
    float sq0 = 0.f, sq1 = 0.f;
    const int KT = K / BK;

    float4 va0, va1, vb0, vnw;
    float4 vb1 = make_float4(0.f, 0.f, 0.f, 0.f);
    va0 = *(const float4*)&A[(size_t)(m0 + arow) * lda + aq * 4];
    va1 = *(const float4*)&A[(size_t)(m0 + arow + 64) * lda + aq * 4];
    vb0 = *(const float4*)&W[(size_t)(n0 + arow) * ldw + aq * 4];
    if (NBCH == 2) vb1 = *(const float4*)&W[(size_t)(n0 + arow + 64) * ldw + aq * 4];
    if (NORMW) vnw = *(const float4*)&nw[aq * 4];

    for (int kt = 0; kt < KT; kt++) {
        const int buf = kt & 1;
        {
            float* d0 = &sA[buf][(aq * 4) * STA + arow];
            d0[0] = va0.x; d0[STA] = va0.y; d0[2 * STA] = va0.z; d0[3 * STA] = va0.w;
            float* d1 = d0 + 64;
            d1[0] = va1.x; d1[STA] = va1.y; d1[2 * STA] = va1.z; d1[3 * STA] = va1.w;
        }
        if (ROWSCALE) {
            sq0 = fmaf(va0.x, va0.x, fmaf(va0.y, va0.y,
                  fmaf(va0.z, va0.z, fmaf(va0.w, va0.w, sq0))));
            sq1 = fmaf(va1.x, va1.x, fmaf(va1.y, va1.y,
                  fmaf(va1.z, va1.z, fmaf(va1.w, va1.w, sq1))));
        }
        {
            float4 b0 = vb0, b1 = vb1;
            if (NORMW) {
                b0.x *= vnw.x; b0.y *= vnw.y; b0.z *= vnw.z; b0.w *= vnw.w;
                if (NBCH == 2) {
                    b1.x *= vnw.x; b1.y *= vnw.y; b1.z *= vnw.z; b1.w *= vnw.w;
                }
            }
            float* d0 = &sB[buf][(aq * 4) * STB + arow];
            d0[0] = b0.x; d0[STB] = b0.y; d0[2 * STB] = b0.z; d0[3 * STB] = b0.w;
            if (NBCH == 2) {
                float* d1 = d0 + 64;
                d1[0] = b1.x; d1[STB] = b1.y; d1[2 * STB] = b1.z; d1[3 * STB] = b1.w;
            }
        }
        __syncthreads();

        if (kt + 1 < KT) {
            const int k0 = (kt + 1) * BK;
            va0 = *(const float4*)&A[(size_t)(m0 + arow) * lda + k0 + aq * 4];
            va1 = *(const float4*)&A[(size_t)(m0 + arow + 64) * lda + k0 + aq * 4];
            vb0 = *(const float4*)&W[(size_t)(n0 + arow) * ldw + k0 + aq * 4];
            if (NBCH == 2)
                vb1 = *(const float4*)&W[(size_t)(n0 + arow + 64) * ldw + k0 + aq * 4];
            if (NORMW) vnw = *(const float4*)&nw[k0 + aq * 4];
        }

        const float* bufA = sA[buf];
        const float* bufB = sB[buf];
        #pragma unroll
        for (int k = 0; k < BK; k++) {
            const ulonglong2 a0 = *(const ulonglong2*)&bufA[k * STA + rb];
            const ulonglong2 a1 = *(const ulonglong2*)&bufA[k * STA + rb + 4];
            const u64t ap[4] = {a0.x, a0.y, a1.x, a1.y};
            float4 b0 = *(const float4*)&bufB[k * STB + cbase];
            float4 b1;
            if (NQ == 2) b1 = *(const float4*)&bufB[k * STB + cbase + 32];
            u64t bd[TC];
            bd[0] = dup2f(b0.x); bd[1] = dup2f(b0.y);
            bd[2] = dup2f(b0.z); bd[3] = dup2f(b0.w);
            if (NQ == 2) {
                bd[4] = dup2f(b1.x); bd[5] = dup2f(b1.y);
                bd[6] = dup2f(b1.z); bd[7] = dup2f(b1.w);
            }
            #pragma unroll
            for (int ih = 0; ih < 4; ih++)
                #pragma unroll
                for (int j = 0; j < TC; j++)
                    ffma2(cpk[ih][j], ap[ih], bd[j]);
        }
        // no trailing sync: top barrier of tile kt+1 already orders
        // compute(kt) before any STS into buf(kt) at tile kt+2.
    }

    if (ROWSCALE) {
        float s0 = sq0 + __shfl_xor_sync(0xffffffffu, sq0, 1);
        s0 += __shfl_xor_sync(0xffffffffu, s0, 2);
        float s1 = sq1 + __shfl_xor_sync(0xffffffffu, sq1, 1);
        s1 += __shfl_xor_sync(0xffffffffu, s1, 2);
        if ((lane & 3) == 0) {
            rbuf[arow]      = rsqrtf(s0 / (float)K + 1e-5f);
            rbuf[arow + 64] = rsqrtf(s1 / (float)K + 1e-5f);
        }
        __syncthreads();
    }

    const bool do_silu = SILUZ && (n0 >= ED);

    float bias_r[TC];
    if (BIAS) {
        #pragma unroll
        for (int q = 0; q < NQ; q++) {
            float4 bb = *(const float4*)&bias[n0 + cbase + q * 32];
            bias_r[q * 4 + 0] = bb.x; bias_r[q * 4 + 1] = bb.y;
            bias_r[q * 4 + 2] = bb.z; bias_r[q * 4 + 3] = bb.w;
        }
    }
    #pragma unroll
    for (int ih = 0; ih < 4; ih++) {
        float lo[TC], hi[TC];
        #pragma unroll
        for (int j = 0; j < TC; j++) {
            float2 f = unpack2(cpk[ih][j]);
            lo[j] = f.x; hi[j] = f.y;
        }
        #pragma unroll
        for (int half = 0; half < 2; half++) {
            const float* src = half ? hi : lo;
            const int rt = rb + 2 * ih + half;
            const int row = m0 + rt;
            const float scale = ROWSCALE ? rbuf[rt] : 1.f;
            #pragma unroll
            for (int q = 0; q < NQ; q++) {
                float* cp = &C[(size_t)row * ldc + n0 + cbase + q * 32];
                float4 v = make_float4(src[q * 4 + 0], src[q * 4 + 1],
                                       src[q * 4 + 2], src[q * 4 + 3]);
                if (ROWSCALE) { v.x *= scale; v.y *= scale; v.z *= scale; v.w *= scale; }
                if (BIAS) {
                    v.x += bias_r[q * 4 + 0]; v.y += bias_r[q * 4 + 1];
                    v.z += bias_r[q * 4 + 2]; v.w += bias_r[q * 4 + 3];
                }
                if (SOFTPLUS) {
                    v.x = softplus_f(v.x); v.y = softplus_f(v.y);
                    v.z = softplus_f(v.z); v.w = softplus_f(v.w);
                }
                if (SILUZ) {
                    if (do_silu) {
                        v.x = silu_f(v.x); v.y = silu_f(v.y);
                        v.z = silu_f(v.z); v.w = silu_f(v.w);
                    }
                }
                if (ACCUM) {
                    float4 o = *(const float4*)cp;
                    v.x += o.x; v.y += o.y; v.z += o.z; v.w += o.w;
                }
                *(float4*)cp = v;
            }
        }
    }
}

// ---------------------------------------------------------------------------
// Reduce 8 split-K partials: out[i] = sum_s part[s][i]  (float4-wide)
// ---------------------------------------------------------------------------
__global__ void reduce8_kernel(const float* __restrict__ part,
                               float* __restrict__ out)
{
    const int i = (blockIdx.x * 256 + threadIdx.x) * 4;
    const int n = NTOK * 64;
    float4 s = *(const float4*)&part[i];
    #pragma unroll
    for (int k = 1; k < 8; k++) {
        float4 v = *(const float4*)&part[i + k * n];
        s.x += v.x; s.y += v.y; s.z += v.z; s.w += v.w;
    }
    *(float4*)&out[i] = s;
}

// ---------------------------------------------------------------------------
// Depthwise causal conv (k=4) + bias + silu (fast-div).
// Each thread: 4 consecutive tokens x 4 channels (7 float4 loads, 16 outputs).
// ---------------------------------------------------------------------------
__device__ __forceinline__ float getc(float4 v, int k) {
    return k == 0 ? v.x : k == 1 ? v.y : k == 2 ? v.z : v.w;
}
__device__ __forceinline__ float4 silu4(float4 a) {
    a.x = silu_f(a.x); a.y = silu_f(a.y);
    a.z = silu_f(a.z); a.w = silu_f(a.w);
    return a;
}

__global__ void conv_kernel(const float* __restrict__ xz,
                            const float* __restrict__ cw,
                            const float* __restrict__ cb,
                            float* __restrict__ out)
{
    const int idx = blockIdx.x * blockDim.x + threadIdx.x;   // NTOK/4 * ED/4
    const int e4 = (idx & 255) << 2;
    const int tq = idx >> 8;                 // token quad
    const int tloc = (tq * 4) & (SEQL - 1);  // local pos of first token

    const float4 bias = *(const float4*)&cb[e4];
    const float4 w0 = *(const float4*)&cw[(e4 + 0) * DCONV];
    const float4 w1 = *(const float4*)&cw[(e4 + 1) * DCONV];
    const float4 w2 = *(const float4*)&cw[(e4 + 2) * DCONV];
    const float4 w3 = *(const float4*)&cw[(e4 + 3) * DCONV];

    float4 xv[7];
    #pragma unroll
    for (int s = 0; s < 7; s++) {
        const int tl = tloc - 3 + s;
        xv[s] = (tl >= 0)
            ? *(const float4*)&xz[((size_t)tq * 4 + (s - 3)) * (2 * ED) + e4]
            : make_float4(0.f, 0.f, 0.f, 0.f);
    }

    #pragma unroll
    for (int o = 0; o < 4; o++) {
        float4 acc = bias;
        #pragma unroll
        for (int k = 0; k < DCONV; k++) {
            const float4 v = xv[o + k];
            acc.x = fmaf(getc(w0, k), v.x, acc.x);
            acc.y = fmaf(getc(w1, k), v.y, acc.y);
            acc.z = fmaf(getc(w2, k), v.z, acc.z);
            acc.w = fmaf(getc(w3, k), v.w, acc.w);
        }
        *(float4*)&out[((size_t)tq * 4 + o) * ED + e4] = silu4(acc);
    }
}

// ---------------------------------------------------------------------------
// Selective scan + gating. One warp = 2 channels; 16 lanes/channel, one state
// per lane (1 MUFU per token per warp). 8-token software pipeline.
// Grid 256 x 128 threads -> 1024 warps (~7/SM) for latency hiding.
// z half of xz is already silu'd by the in_proj epilogue (SILUZ).
// ---------------------------------------------------------------------------
__global__ __launch_bounds__(128) void scan_kernel(
    const float* __restrict__ delta,
    const float* __restrict__ xi,
    const float* __restrict__ dbc,
    const float* __restrict__ xz,
    const float* __restrict__ A_log,
    const float* __restrict__ Dp,
    float* __restrict__ y)
{
    const int lane = threadIdx.x & 31;
    const int warp = threadIdx.x >> 5;
    const int ch = lane >> 4;                 // channel within warp (0..1)
    const int n  = lane & 15;                 // state
    const int c = blockIdx.x * 8 + warp * 2 + ch;
    const int b = c >> 10;
    const int e = c & (ED - 1);

    const float a  = -__expf(A_log[e * DSTATE + n]);
    const float Dv = Dp[e];

    const float* dptr = delta + (size_t)b * SEQL * ED + e;
    const float* xptr = xi    + (size_t)b * SEQL * ED + e;
    const float* bcp  = dbc   + (size_t)b * SEQL * 64 + DTRANK + n;
    const float* zptr = xz    + (size_t)b * SEQL * (2 * ED) + ED + e;
    float*       yptr = y     + (size_t)b * SEQL * ED + e;

    constexpr int PF = 8;
    float cdv[PF], cxv[PF], czv[PF], cB[PF], cC[PF];
    #pragma unroll
    for (int i = 0; i < PF; i++) {
        cdv[i] = __ldg(&dptr[(size_t)i * ED]);
        cxv[i] = __ldg(&xptr[(size_t)i * ED]);
        czv[i] = __ldg(&zptr[(size_t)i * (2 * ED)]);
        cB[i] = __ldg(&bcp[i * 64]);
        cC[i] = __ldg(&bcp[i * 64 + DSTATE]);
    }

    float hs = 0.f;
    for (int t0 = 0; t0 < SEQL; t0 += PF) {
        float ndv[PF], nxv[PF], nzv[PF], nB[PF], nC[PF];
        if (t0 + PF < SEQL) {
            #pragma unroll
            for (int i = 0; i < PF; i++) {
                const int t = t0 + PF + i;
                ndv[i] = __ldg(&dptr[(size_t)t * ED]);
                nxv[i] = __ldg(&xptr[(size_t)t * ED]);
                nzv[i] = __ldg(&zptr[(size_t)t * (2 * ED)]);
                nB[i] = __ldg(&bcp[t * 64]);
                nC[i] = __ldg(&bcp[t * 64 + DSTATE]);
            }
        }
        #pragma unroll
        for (int i = 0; i < PF; i++) {
            const float dA = __expf(cdv[i] * a);
            hs = fmaf(dA, hs, cdv[i] * cxv[i] * cB[i]);
            float p = hs * cC[i];
            p += __shfl_xor_sync(0xffffffffu, p, 8);
            p += __shfl_xor_sync(0xffffffffu, p, 4);
            p += __shfl_xor_sync(0xffffffffu, p, 2);
            p += __shfl_xor_sync(0xffffffffu, p, 1);
            if (n == 0) {
                // czv already = silu(z) (applied in in_proj epilogue)
                yptr[(size_t)(t0 + i) * ED] = (p + Dv * cxv[i]) * czv[i];
            }
        }
        #pragma unroll
        for (int i = 0; i < PF; i++) {
            cdv[i] = ndv[i]; cxv[i] = nxv[i]; czv[i] = nzv[i];
            cB[i] = nB[i]; cC[i] = nC[i];
        }
    }
}

// ---------------------------------------------------------------------------
// Host launch
// ---------------------------------------------------------------------------
extern "C" void kernel_launch(void* const* d_in, const int* in_sizes, int n_in,
                              void* d_out, int out_size)
{
    const float* x        = (const float*)d_in[0];
    const float* emb_w    = (const float*)d_in[1];
    const float* emb_b    = (const float*)d_in[2];
    const float* in_w     = (const float*)d_in[3];
    const float* conv_w   = (const float*)d_in[4];
    const float* conv_b   = (const float*)d_in[5];
    const float* xp_w     = (const float*)d_in[6];
    const float* dt_w     = (const float*)d_in[7];
    const float* dt_b     = (const float*)d_in[8];
    const float* A_log    = (const float*)d_in[9];
    const float* Dparam   = (const float*)d_in[10];
    const float* out_w    = (const float*)d_in[11];
    const float* norm_w   = (const float*)d_in[12];
    float* h = (float*)d_out;

    float *xz, *xic, *dbc, *dbcp, *delta, *yb;
    cudaGetSymbolAddress((void**)&xz,    g_xz);
    cudaGetSymbolAddress((void**)&xic,   g_xic);
    cudaGetSymbolAddress((void**)&dbc,   g_dbc);
    cudaGetSymbolAddress((void**)&dbcp,  g_dbcp);
    cudaGetSymbolAddress((void**)&delta, g_delta);
    cudaGetSymbolAddress((void**)&yb,    g_y);

    // Embedding: h = x @ emb_w^T + emb_b  (M=4096, N=512, K=64)
    fgemm<128, true, false, false, false, false>
        <<<dim3(DMODEL / 128, NTOK / 128), 256>>>(
        x, 64, emb_w, 64, emb_b, nullptr, h, DMODEL, 64);

    for (int layer = 0; layer < NLAYERS; layer++) {
        const float* l_in_w   = in_w   + (size_t)layer * 2 * ED * DMODEL;
        const float* l_conv_w = conv_w + (size_t)layer * ED * DCONV;
        const float* l_conv_b = conv_b + (size_t)layer * ED;
        const float* l_xp_w   = xp_w   + (size_t)layer * 64 * ED;
        const float* l_dt_w   = dt_w   + (size_t)layer * ED * DTRANK;
        const float* l_dt_b   = dt_b   + (size_t)layer * ED;
        const float* l_A_log  = A_log  + (size_t)layer * ED * DSTATE;
        const float* l_D      = Dparam + (size_t)layer * ED;
        const float* l_out_w  = out_w  + (size_t)layer * DMODEL * ED;
        const float* l_norm_w = norm_w + (size_t)layer * DMODEL;

        // 1+2. xz = rmsnorm(h) @ in_proj^T, norm fused; z half gets silu
        //      in the epilogue (M=4096, N=2048, K=512)
        fgemm<128, false, false, false, true, true, 1, true>
            <<<dim3(2 * ED / 128, NTOK / 128), 256>>>(
            h, DMODEL, l_in_w, DMODEL, nullptr, l_norm_w, xz, 2 * ED, DMODEL);

        // 3. xi = silu(conv(xz[:, :ED]) + cb)
        conv_kernel<<<(NTOK / 4) * (ED / 4) / 256, 256>>>(
            xz, l_conv_w, l_conv_b, xic);

        // 4. dbc = xi @ x_proj^T  (M=4096, N=64, K=1024) — split-K=8
        fgemm<64, false, false, false, false, false, 8>
            <<<dim3(1, NTOK / 128, 8), 256>>>(
            xic, ED, l_xp_w, ED, nullptr, nullptr, dbcp, 64, ED);
        reduce8_kernel<<<(NTOK * 64 / 4) / 256, 256>>>(dbcp, dbc);

        // 5. delta = softplus(dbc[:, :32] @ dt_proj^T + dt_b)  (M=4096, N=1024, K=32)
        fgemm<128, true, false, true, false, false>
            <<<dim3(ED / 128, NTOK / 128), 256>>>(
            dbc, 64, l_dt_w, DTRANK, l_dt_b, nullptr, delta, ED, DTRANK);

        // 6. scan + gating -> y  (z pre-silu'd)
        scan_kernel<<<(BATCH * ED) / 8, 128>>>(delta, xic, dbc, xz,
                                               l_A_log, l_D, yb);

        // 7. h += y @ out_proj^T  (M=4096, N=512, K=1024)
        fgemm<128, false, true, false, false, false>
            <<<dim3(DMODEL / 128, NTOK / 128), 256>>>(
            yb, ED, l_out_w, ED, nullptr, nullptr, h, DMODEL, ED);
    }
}

// round 12
// speedup vs baseline: 1.0535x; 1.0535x over previous
#include <cuda_runtime.h>
#include <math.h>
#include <cstdint>

// Problem constants
#define BATCH 2
#define SEQL 2048
#define NTOK (BATCH * SEQL)          // 4096
#define DMODEL 512
#define ED 1024
#define DSTATE 16
#define DCONV 4
#define DTRANK 32
#define NLAYERS 2

// Scratch buffers (no cudaMalloc allowed)
__device__ float g_xz[NTOK * 2 * ED];
__device__ float g_xic[NTOK * ED];
__device__ float g_dbc[NTOK * 64];
__device__ float g_dbcp[8 * NTOK * 64];   // split-K partials for x_proj
__device__ float g_delta[NTOK * ED];
__device__ float g_y[NTOK * ED];

__device__ __forceinline__ float softplus_f(float v) {
    return (v > 20.f) ? v : log1pf(__expf(v));
}
__device__ __forceinline__ float silu_f(float v) {
    return __fdividef(v, 1.f + __expf(-v));
}

// ---------------------------------------------------------------------------
// Packed fp32 helpers (Blackwell f32x2)
// ---------------------------------------------------------------------------
typedef unsigned long long u64t;

__device__ __forceinline__ u64t dup2f(float v) {
    u64t r; unsigned u = __float_as_uint(v);
    asm("mov.b64 %0, {%1, %1};" : "=l"(r) : "r"(u));
    return r;
}
__device__ __forceinline__ void ffma2(u64t& c, u64t a, u64t b) {
    asm("fma.rn.f32x2 %0, %1, %2, %0;" : "+l"(c) : "l"(a), "l"(b));
}
__device__ __forceinline__ float2 unpack2(u64t p) {
    unsigned lo, hi;
    asm("mov.b64 {%0, %1}, %2;" : "=r"(lo), "=r"(hi) : "l"(p));
    return make_float2(__uint_as_float(lo), __uint_as_float(hi));
}

// ---------------------------------------------------------------------------
// fp32 FFMA2 GEMM:  C[M,N] (=, +=) A[M,K] @ W[N,K]^T   (R10 configuration)
// BM=128, BN=TILE_N (128/64), BK=16, 256 threads, smem k-major double buffer,
// two __syncthreads per k-tile. B-fragment columns split into 4-wide groups
// 32 apart (TC=8): conflict-free LDS.128.
// Options: +bias, +softplus, NORMW, ROWSCALE, SPLITK, SILUZ (silu on n0>=ED).
// ---------------------------------------------------------------------------
template <int TILE_N, bool BIAS, bool ACCUM, bool SOFTPLUS, bool NORMW,
          bool ROWSCALE, int SPLITK = 1, bool SILUZ = false>
__global__ __launch_bounds__(256) void fgemm(
    const float* __restrict__ A, int lda,
    const float* __restrict__ W, int ldw,
    const float* __restrict__ bias,
    const float* __restrict__ nw,
    float* __restrict__ C, int ldc, int K)
{
    constexpr int BK = 16, STA = 132, STB = TILE_N + 4;
    constexpr int NBCH = TILE_N / 64;
    constexpr int TC = TILE_N / 16;
    constexpr int NQ = TC / 4;

    __shared__ float sA[2][BK * STA];
    __shared__ float sB[2][BK * STB];
    __shared__ float rbuf[128];

    const int tid = threadIdx.x;
    const int wid = tid >> 5, lane = tid & 31;
    const int ly = lane >> 3, lx = lane & 7;
    const int wy = wid >> 1, wx = wid & 1;
    const int rb = wy * 32 + ly * 8;
    const int cbase = wx * (TILE_N / 2) + lx * 4;
    const int m0 = blockIdx.y * 128;
    const int n0 = blockIdx.x * TILE_N;

    if (SPLITK > 1) {
        const int ks = blockIdx.z * (K / SPLITK);
        A += ks; W += ks;
        C += (size_t)blockIdx.z * gridDim.y * 128 * ldc;
        K = K / SPLITK;
    }

    const int arow = tid >> 2, aq = tid & 3;

    u64t cpk[4][TC] = {};
    float sq0 = 0.f, sq1 = 0.f;
    const int KT = K / BK;

    float4 va0, va1, vb0, vnw;
    float4 vb1 = make_float4(0.f, 0.f, 0.f, 0.f);
    va0 = *(const float4*)&A[(size_t)(m0 + arow) * lda + aq * 4];
    va1 = *(const float4*)&A[(size_t)(m0 + arow + 64) * lda + aq * 4];
    vb0 = *(const float4*)&W[(size_t)(n0 + arow) * ldw + aq * 4];
    if (NBCH == 2) vb1 = *(const float4*)&W[(size_t)(n0 + arow + 64) * ldw + aq * 4];
    if (NORMW) vnw = *(const float4*)&nw[aq * 4];

    for (int kt = 0; kt < KT; kt++) {
        const int buf = kt & 1;
        {
            float* d0 = &sA[buf][(aq * 4) * STA + arow];
            d0[0] = va0.x; d0[STA] = va0.y; d0[2 * STA] = va0.z; d0[3 * STA] = va0.w;
            float* d1 = d0 + 64;
            d1[0] = va1.x; d1[STA] = va1.y; d1[2 * STA] = va1.z; d1[3 * STA] = va1.w;
        }
        if (ROWSCALE) {
            sq0 = fmaf(va0.x, va0.x, fmaf(va0.y, va0.y,
                  fmaf(va0.z, va0.z, fmaf(va0.w, va0.w, sq0))));
            sq1 = fmaf(va1.x, va1.x, fmaf(va1.y, va1.y,
                  fmaf(va1.z, va1.z, fmaf(va1.w, va1.w, sq1))));
        }
        {
            float4 b0 = vb0, b1 = vb1;
            if (NORMW) {
                b0.x *= vnw.x; b0.y *= vnw.y; b0.z *= vnw.z; b0.w *= vnw.w;
                if (NBCH == 2) {
                    b1.x *= vnw.x; b1.y *= vnw.y; b1.z *= vnw.z; b1.w *= vnw.w;
                }
            }
            float* d0 = &sB[buf][(aq * 4) * STB + arow];
            d0[0] = b0.x; d0[STB] = b0.y; d0[2 * STB] = b0.z; d0[3 * STB] = b0.w;
            if (NBCH == 2) {
                float* d1 = d0 + 64;
                d1[0] = b1.x; d1[STB] = b1.y; d1[2 * STB] = b1.z; d1[3 * STB] = b1.w;
            }
        }
        __syncthreads();

        if (kt + 1 < KT) {
            const int k0 = (kt + 1) * BK;
            va0 = *(const float4*)&A[(size_t)(m0 + arow) * lda + k0 + aq * 4];
            va1 = *(const float4*)&A[(size_t)(m0 + arow + 64) * lda + k0 + aq * 4];
            vb0 = *(const float4*)&W[(size_t)(n0 + arow) * ldw + k0 + aq * 4];
            if (NBCH == 2)
                vb1 = *(const float4*)&W[(size_t)(n0 + arow + 64) * ldw + k0 + aq * 4];
            if (NORMW) vnw = *(const float4*)&nw[k0 + aq * 4];
        }

        const float* bufA = sA[buf];
        const float* bufB = sB[buf];
        #pragma unroll
        for (int k = 0; k < BK; k++) {
            const ulonglong2 a0 = *(const ulonglong2*)&bufA[k * STA + rb];
            const ulonglong2 a1 = *(const ulonglong2*)&bufA[k * STA + rb + 4];
            const u64t ap[4] = {a0.x, a0.y, a1.x, a1.y};
            float4 b0 = *(const float4*)&bufB[k * STB + cbase];
            float4 b1;
            if (NQ == 2) b1 = *(const float4*)&bufB[k * STB + cbase + 32];
            u64t bd[TC];
            bd[0] = dup2f(b0.x); bd[1] = dup2f(b0.y);
            bd[2] = dup2f(b0.z); bd[3] = dup2f(b0.w);
            if (NQ == 2) {
                bd[4] = dup2f(b1.x); bd[5] = dup2f(b1.y);
                bd[6] = dup2f(b1.z); bd[7] = dup2f(b1.w);
            }
            #pragma unroll
            for (int ih = 0; ih < 4; ih++)
                #pragma unroll
                for (int j = 0; j < TC; j++)
                    ffma2(cpk[ih][j], ap[ih], bd[j]);
        }
        __syncthreads();
    }

    if (ROWSCALE) {
        float s0 = sq0 + __shfl_xor_sync(0xffffffffu, sq0, 1);
        s0 += __shfl_xor_sync(0xffffffffu, s0, 2);
        float s1 = sq1 + __shfl_xor_sync(0xffffffffu, sq1, 1);
        s1 += __shfl_xor_sync(0xffffffffu, s1, 2);
        if ((lane & 3) == 0) {
            rbuf[arow]      = rsqrtf(s0 / (float)K + 1e-5f);
            rbuf[arow + 64] = rsqrtf(s1 / (float)K + 1e-5f);
        }
        __syncthreads();
    }

    const bool do_silu = SILUZ && (n0 >= ED);

    float bias_r[TC];
    if (BIAS) {
        #pragma unroll
        for (int q = 0; q < NQ; q++) {
            float4 bb = *(const float4*)&bias[n0 + cbase + q * 32];
            bias_r[q * 4 + 0] = bb.x; bias_r[q * 4 + 1] = bb.y;
            bias_r[q * 4 + 2] = bb.z; bias_r[q * 4 + 3] = bb.w;
        }
    }
    #pragma unroll
    for (int ih = 0; ih < 4; ih++) {
        float lo[TC], hi[TC];
        #pragma unroll
        for (int j = 0; j < TC; j++) {
            float2 f = unpack2(cpk[ih][j]);
            lo[j] = f.x; hi[j] = f.y;
        }
        #pragma unroll
        for (int half = 0; half < 2; half++) {
            const float* src = half ? hi : lo;
            const int rt = rb + 2 * ih + half;
            const int row = m0 + rt;
            const float scale = ROWSCALE ? rbuf[rt] : 1.f;
            #pragma unroll
            for (int q = 0; q < NQ; q++) {
                float* cp = &C[(size_t)row * ldc + n0 + cbase + q * 32];
                float4 v = make_float4(src[q * 4 + 0], src[q * 4 + 1],
                                       src[q * 4 + 2], src[q * 4 + 3]);
                if (ROWSCALE) { v.x *= scale; v.y *= scale; v.z *= scale; v.w *= scale; }
                if (BIAS) {
                    v.x += bias_r[q * 4 + 0]; v.y += bias_r[q * 4 + 1];
                    v.z += bias_r[q * 4 + 2]; v.w += bias_r[q * 4 + 3];
                }
                if (SOFTPLUS) {
                    v.x = softplus_f(v.x); v.y = softplus_f(v.y);
                    v.z = softplus_f(v.z); v.w = softplus_f(v.w);
                }
                if (SILUZ) {
                    if (do_silu) {
                        v.x = silu_f(v.x); v.y = silu_f(v.y);
                        v.z = silu_f(v.z); v.w = silu_f(v.w);
                    }
                }
                if (ACCUM) {
                    float4 o = *(const float4*)cp;
                    v.x += o.x; v.y += o.y; v.z += o.z; v.w += o.w;
                }
                *(float4*)cp = v;
            }
        }
    }
}

// ---------------------------------------------------------------------------
// Reduce 8 split-K partials: out[i] = sum_s part[s][i]  (float4-wide)
// ---------------------------------------------------------------------------
__global__ void reduce8_kernel(const float* __restrict__ part,
                               float* __restrict__ out)
{
    const int i = (blockIdx.x * 256 + threadIdx.x) * 4;
    const int n = NTOK * 64;
    float4 s = *(const float4*)&part[i];
    #pragma unroll
    for (int k = 1; k < 8; k++) {
        float4 v = *(const float4*)&part[i + k * n];
        s.x += v.x; s.y += v.y; s.z += v.z; s.w += v.w;
    }
    *(float4*)&out[i] = s;
}

// ---------------------------------------------------------------------------
// Depthwise causal conv (k=4) + bias + silu (fast-div).
// Each thread: 4 consecutive tokens x 4 channels (7 float4 loads, 16 outputs).
// ---------------------------------------------------------------------------
__device__ __forceinline__ float getc(float4 v, int k) {
    return k == 0 ? v.x : k == 1 ? v.y : k == 2 ? v.z : v.w;
}
__device__ __forceinline__ float4 silu4(float4 a) {
    a.x = silu_f(a.x); a.y = silu_f(a.y);
    a.z = silu_f(a.z); a.w = silu_f(a.w);
    return a;
}

__global__ void conv_kernel(const float* __restrict__ xz,
                            const float* __restrict__ cw,
                            const float* __restrict__ cb,
                            float* __restrict__ out)
{
    const int idx = blockIdx.x * blockDim.x + threadIdx.x;   // NTOK/4 * ED/4
    const int e4 = (idx & 255) << 2;
    const int tq = idx >> 8;                 // token quad
    const int tloc = (tq * 4) & (SEQL - 1);  // local pos of first token

    const float4 bias = *(const float4*)&cb[e4];
    const float4 w0 = *(const float4*)&cw[(e4 + 0) * DCONV];
    const float4 w1 = *(const float4*)&cw[(e4 + 1) * DCONV];
    const float4 w2 = *(const float4*)&cw[(e4 + 2) * DCONV];
    const float4 w3 = *(const float4*)&cw[(e4 + 3) * DCONV];

    float4 xv[7];
    #pragma unroll
    for (int s = 0; s < 7; s++) {
        const int tl = tloc - 3 + s;
        xv[s] = (tl >= 0)
            ? *(const float4*)&xz[((size_t)tq * 4 + (s - 3)) * (2 * ED) + e4]
            : make_float4(0.f, 0.f, 0.f, 0.f);
    }

    #pragma unroll
    for (int o = 0; o < 4; o++) {
        float4 acc = bias;
        #pragma unroll
        for (int k = 0; k < DCONV; k++) {
            const float4 v = xv[o + k];
            acc.x = fmaf(getc(w0, k), v.x, acc.x);
            acc.y = fmaf(getc(w1, k), v.y, acc.y);
            acc.z = fmaf(getc(w2, k), v.z, acc.z);
            acc.w = fmaf(getc(w3, k), v.w, acc.w);
        }
        *(float4*)&out[((size_t)tq * 4 + o) * ED + e4] = silu4(acc);
    }
}

// ---------------------------------------------------------------------------
// Selective scan + gating (R10 layout). One warp = 4 channels; 8 lanes per
// channel, each lane owns an adjacent state pair (LDG.64 B/C). 8-token
// software pipeline. z half of xz already silu'd (SILUZ epilogue).
// ---------------------------------------------------------------------------
__global__ __launch_bounds__(128) void scan_kernel(
    const float* __restrict__ delta,
    const float* __restrict__ xi,
    const float* __restrict__ dbc,
    const float* __restrict__ xz,
    const float* __restrict__ A_log,
    const float* __restrict__ Dp,
    float* __restrict__ y)
{
    const int lane = threadIdx.x & 31;
    const int warp = threadIdx.x >> 5;
    const int ch = lane >> 3;                 // channel within warp
    const int j  = lane & 7;                  // state pair (2j, 2j+1)
    const int c = blockIdx.x * 16 + warp * 4 + ch;
    const int b = c >> 10;
    const int e = c & (ED - 1);

    const float a0 = -__expf(A_log[e * DSTATE + 2 * j]);
    const float a1 = -__expf(A_log[e * DSTATE + 2 * j + 1]);
    const float Dv = Dp[e];

    const float* dptr = delta + (size_t)b * SEQL * ED + e;
    const float* xptr = xi    + (size_t)b * SEQL * ED + e;
    const float* bcp  = dbc   + (size_t)b * SEQL * 64 + DTRANK + 2 * j;
    const float* zptr = xz    + (size_t)b * SEQL * (2 * ED) + ED + e;
    float*       yptr = y     + (size_t)b * SEQL * ED + e;

    constexpr int PF = 8;
    float cdv[PF], cxv[PF], czv[PF];
    float2 cB[PF], cC[PF];
    #pragma unroll
    for (int i = 0; i < PF; i++) {
        cdv[i] = __ldg(&dptr[(size_t)i * ED]);
        cxv[i] = __ldg(&xptr[(size_t)i * ED]);
        czv[i] = __ldg(&zptr[(size_t)i * (2 * ED)]);
        cB[i] = __ldg((const float2*)&bcp[i * 64]);
        cC[i] = __ldg((const float2*)&bcp[i * 64 + DSTATE]);
    }

    float h0 = 0.f, h1 = 0.f;
    for (int t0 = 0; t0 < SEQL; t0 += PF) {
        float ndv[PF], nxv[PF], nzv[PF];
        float2 nB[PF], nC[PF];
        if (t0 + PF < SEQL) {
            #pragma unroll
            for (int i = 0; i < PF; i++) {
                const int t = t0 + PF + i;
                ndv[i] = __ldg(&dptr[(size_t)t * ED]);
                nxv[i] = __ldg(&xptr[(size_t)t * ED]);
                nzv[i] = __ldg(&zptr[(size_t)t * (2 * ED)]);
                nB[i] = __ldg((const float2*)&bcp[t * 64]);
                nC[i] = __ldg((const float2*)&bcp[t * 64 + DSTATE]);
            }
        }
        #pragma unroll
        for (int i = 0; i < PF; i++) {
            const float dA0 = __expf(cdv[i] * a0);
            const float dA1 = __expf(cdv[i] * a1);
            const float u = cdv[i] * cxv[i];
            h0 = fmaf(dA0, h0, u * cB[i].x);
            h1 = fmaf(dA1, h1, u * cB[i].y);
            float p = fmaf(h1, cC[i].y, h0 * cC[i].x);
            p += __shfl_xor_sync(0xffffffffu, p, 4);
            p += __shfl_xor_sync(0xffffffffu, p, 2);
            p += __shfl_xor_sync(0xffffffffu, p, 1);
            if (j == 0) {
                // czv already = silu(z) (applied in in_proj epilogue)
                yptr[(size_t)(t0 + i) * ED] = (p + Dv * cxv[i]) * czv[i];
            }
        }
        #pragma unroll
        for (int i = 0; i < PF; i++) {
            cdv[i] = ndv[i]; cxv[i] = nxv[i]; czv[i] = nzv[i];
            cB[i] = nB[i]; cC[i] = nC[i];
        }
    }
}

// ---------------------------------------------------------------------------
// Host launch
// ---------------------------------------------------------------------------
extern "C" void kernel_launch(void* const* d_in, const int* in_sizes, int n_in,
                              void* d_out, int out_size)
{
    const float* x        = (const float*)d_in[0];
    const float* emb_w    = (const float*)d_in[1];
    const float* emb_b    = (const float*)d_in[2];
    const float* in_w     = (const float*)d_in[3];
    const float* conv_w   = (const float*)d_in[4];
    const float* conv_b   = (const float*)d_in[5];
    const float* xp_w     = (const float*)d_in[6];
    const float* dt_w     = (const float*)d_in[7];
    const float* dt_b     = (const float*)d_in[8];
    const float* A_log    = (const float*)d_in[9];
    const float* Dparam   = (const float*)d_in[10];
    const float* out_w    = (const float*)d_in[11];
    const float* norm_w   = (const float*)d_in[12];
    float* h = (float*)d_out;

    float *xz, *xic, *dbc, *dbcp, *delta, *yb;
    cudaGetSymbolAddress((void**)&xz,    g_xz);
    cudaGetSymbolAddress((void**)&xic,   g_xic);
    cudaGetSymbolAddress((void**)&dbc,   g_dbc);
    cudaGetSymbolAddress((void**)&dbcp,  g_dbcp);
    cudaGetSymbolAddress((void**)&delta, g_delta);
    cudaGetSymbolAddress((void**)&yb,    g_y);

    // Embedding: h = x @ emb_w^T + emb_b  (M=4096, N=512, K=64)
    fgemm<128, true, false, false, false, false>
        <<<dim3(DMODEL / 128, NTOK / 128), 256>>>(
        x, 64, emb_w, 64, emb_b, nullptr, h, DMODEL, 64);

    for (int layer = 0; layer < NLAYERS; layer++) {
        const float* l_in_w   = in_w   + (size_t)layer * 2 * ED * DMODEL;
        const float* l_conv_w = conv_w + (size_t)layer * ED * DCONV;
        const float* l_conv_b = conv_b + (size_t)layer * ED;
        const float* l_xp_w   = xp_w   + (size_t)layer * 64 * ED;
        const float* l_dt_w   = dt_w   + (size_t)layer * ED * DTRANK;
        const float* l_dt_b   = dt_b   + (size_t)layer * ED;
        const float* l_A_log  = A_log  + (size_t)layer * ED * DSTATE;
        const float* l_D      = Dparam + (size_t)layer * ED;
        const float* l_out_w  = out_w  + (size_t)layer * DMODEL * ED;
        const float* l_norm_w = norm_w + (size_t)layer * DMODEL;

        // 1+2. xz = rmsnorm(h) @ in_proj^T, norm fused; z half gets silu
        //      in the epilogue (M=4096, N=2048, K=512)
        fgemm<128, false, false, false, true, true, 1, true>
            <<<dim3(2 * ED / 128, NTOK / 128), 256>>>(
            h, DMODEL, l_in_w, DMODEL, nullptr, l_norm_w, xz, 2 * ED, DMODEL);

        // 3. xi = silu(conv(xz[:, :ED]) + cb)
        conv_kernel<<<(NTOK / 4) * (ED / 4) / 256, 256>>>(
            xz, l_conv_w, l_conv_b, xic);

        // 4. dbc = xi @ x_proj^T  (M=4096, N=64, K=1024) — split-K=8
        fgemm<64, false, false, false, false, false, 8>
            <<<dim3(1, NTOK / 128, 8), 256>>>(
            xic, ED, l_xp_w, ED, nullptr, nullptr, dbcp, 64, ED);
        reduce8_kernel<<<(NTOK * 64 / 4) / 256, 256>>>(dbcp, dbc);

        // 5. delta = softplus(dbc[:, :32] @ dt_proj^T + dt_b)  (M=4096, N=1024, K=32)
        fgemm<128, true, false, true, false, false>
            <<<dim3(ED / 128, NTOK / 128), 256>>>(
            dbc, 64, l_dt_w, DTRANK, l_dt_b, nullptr, delta, ED, DTRANK);

        // 6. scan + gating -> y  (z pre-silu'd)
        scan_kernel<<<(BATCH * ED) / 16, 128>>>(delta, xic, dbc, xz,
                                                l_A_log, l_D, yb);

        // 7. h += y @ out_proj^T  (M=4096, N=512, K=1024)
        fgemm<128, false, true, false, false, false>
            <<<dim3(DMODEL / 128, NTOK / 128), 256>>>(
            yb, ED, l_out_w, ED, nullptr, nullptr, h, DMODEL, ED);
    }
}